// round 13
// baseline (speedup 1.0000x reference)
#include <cuda_runtime.h>
#include <cuda_bf16.h>
#include <cstdint>

#define B_   8
#define C_   256
#define CQ_  32
#define H_   128
#define W_   128
#define HW_  (H_*W_)

typedef unsigned long long u64;

// ---------------- scratch ----------------------------------------------------
__device__ float g_qc [(size_t)B_*HW_*CQ_];   // [b, p(=h*W+w), c]
__device__ float g_kc [(size_t)B_*HW_*CQ_];   // [b, p, c]
__device__ float g_v  [(size_t)B_*C_*HW_];    // [b, c, h, w]
__device__ float g_vt [(size_t)B_*C_*HW_];    // [b, c, w, h]
__device__ float g_att[(size_t)B_*H_*W_*256]; // [b,h,w, 0:128=H, 128:256=W]
__device__ float g_oht[(size_t)B_*C_*HW_];    // outH transposed: [b,c,w,h]
__device__ float g_ow [(size_t)B_*C_*HW_];    // outW: [b,c,h,w]

#define NEGF (__int_as_float(0xff800000))

// ---------------- packed fp32x2 helpers --------------------------------------
__device__ __forceinline__ void fma2(u64& d, u64 a, u64 b) {
    asm("fma.rn.f32x2 %0, %1, %2, %0;" : "+l"(d) : "l"(a), "l"(b));
}
__device__ __forceinline__ float hadd2(u64 v) {
    float lo, hi;
    asm("mov.b64 {%0,%1}, %2;" : "=f"(lo), "=f"(hi) : "l"(v));
    return lo + hi;
}

// ---------------- bf16 split helpers ------------------------------------------
__device__ __forceinline__ u64 pack4bf(__nv_bfloat16 a, __nv_bfloat16 b,
                                        __nv_bfloat16 c, __nv_bfloat16 d) {
    unsigned lo = ((unsigned)__bfloat16_as_ushort(b) << 16) | __bfloat16_as_ushort(a);
    unsigned hi = ((unsigned)__bfloat16_as_ushort(d) << 16) | __bfloat16_as_ushort(c);
    return (u64)lo | ((u64)hi << 32);
}
__device__ __forceinline__ void split4(float4 v, u64& hi, u64& lo) {
    __nv_bfloat16 h0 = __float2bfloat16(v.x), h1 = __float2bfloat16(v.y);
    __nv_bfloat16 h2 = __float2bfloat16(v.z), h3 = __float2bfloat16(v.w);
    __nv_bfloat16 l0 = __float2bfloat16(v.x - __bfloat162float(h0));
    __nv_bfloat16 l1 = __float2bfloat16(v.y - __bfloat162float(h1));
    __nv_bfloat16 l2 = __float2bfloat16(v.z - __bfloat162float(h2));
    __nv_bfloat16 l3 = __float2bfloat16(v.w - __bfloat162float(h3));
    hi = pack4bf(h0, h1, h2, h3);
    lo = pack4bf(l0, l1, l2, l3);
}
__device__ __forceinline__ void mma16816(float c[4], const unsigned a[4], const unsigned b[2]) {
    asm volatile(
        "mma.sync.aligned.m16n8k16.row.col.f32.bf16.bf16.f32 "
        "{%0,%1,%2,%3}, {%4,%5,%6,%7}, {%8,%9}, {%0,%1,%2,%3};"
        : "+f"(c[0]), "+f"(c[1]), "+f"(c[2]), "+f"(c[3])
        : "r"(a[0]), "r"(a[1]), "r"(a[2]), "r"(a[3]), "r"(b[0]), "r"(b[1]));
}

#define KP    136
#define TILEB (128 * KP * 2)
#define OFF_T0 0
#define OFF_T1 (TILEB)
#define OFF_T2 (2 * TILEB)
#define OFF_T3 (3 * TILEB)
#define SMEM_MMA (4 * TILEB)              // 139264

// QK tiles (K=32), pitch 40 bf16
#define KQ    40
#define QTB   (128 * KQ * 2)              // 10240
#define OFF_QHI 0
#define OFF_QLO (QTB)
#define OFF_KHI (2 * QTB)
#define OFF_KLO (3 * QTB)
#define SMEM_E  (128 * 132 * 4)           // 67584 (>= 4*QTB, reused as Es stage)

__device__ __forceinline__ void ldfragA(const char* sm, int hiOff, int loOff,
                                        int rb, int k0, int tig, int kp,
                                        unsigned aH[4], unsigned aL[4]) {
    uint32_t o0 = (uint32_t)(rb * kp + k0 + tig * 2) * 2;
    uint32_t o1 = o0 + 8 * kp * 2;
    aH[0] = *(const unsigned*)(sm + hiOff + o0);
    aH[1] = *(const unsigned*)(sm + hiOff + o1);
    aH[2] = *(const unsigned*)(sm + hiOff + o0 + 16);
    aH[3] = *(const unsigned*)(sm + hiOff + o1 + 16);
    aL[0] = *(const unsigned*)(sm + loOff + o0);
    aL[1] = *(const unsigned*)(sm + loOff + o1);
    aL[2] = *(const unsigned*)(sm + loOff + o0 + 16);
    aL[3] = *(const unsigned*)(sm + loOff + o1 + 16);
}
__device__ __forceinline__ void ldfragB(const char* sm, int hiOff, int loOff,
                                        int xb, int k0, int tig, int kp,
                                        unsigned bH[2], unsigned bL[2]) {
    uint32_t o0 = (uint32_t)(xb * kp + k0 + tig * 2) * 2;
    bH[0] = *(const unsigned*)(sm + hiOff + o0);
    bH[1] = *(const unsigned*)(sm + hiOff + o0 + 16);
    bL[0] = *(const unsigned*)(sm + loOff + o0);
    bL[1] = *(const unsigned*)(sm + loOff + o0 + 16);
}

// ---------------- exact 64th-largest, 4 rows, packed counts + early exit -----
__device__ __forceinline__ void topk64x4(const float v[4][4], float thr[4])
{
    unsigned keys[4][4];
    #pragma unroll
    for (int r = 0; r < 4; ++r)
        #pragma unroll
        for (int j = 0; j < 4; ++j) {
            unsigned u = __float_as_uint(v[r][j]);
            keys[r][j] = (u & 0x80000000u) ? ~u : (u | 0x80000000u);
        }
    unsigned prefix[4] = {0, 0, 0, 0};
    unsigned need[4]   = {64, 64, 64, 64};
    unsigned cand[4]   = {128, 128, 128, 128};
    int      ebit[4]   = {0, 0, 0, 0};
    unsigned done = 0;

    for (int bit = 31; bit >= 0; --bit) {
        unsigned packed = 0;
        #pragma unroll
        for (int r = 0; r < 4; ++r) {
            if (!(done & (1u << r))) {
                unsigned want = (prefix[r] >> bit) | 1u;
                unsigned c = 0;
                #pragma unroll
                for (int j = 0; j < 4; ++j)
                    c += (unsigned)((keys[r][j] >> bit) == want);
                packed += c << (8 * r);
            }
        }
        packed = __reduce_add_sync(0xffffffffu, packed);
        #pragma unroll
        for (int r = 0; r < 4; ++r) {
            if (!(done & (1u << r))) {
                unsigned c = (packed >> (8 * r)) & 255u;
                if (c >= need[r]) { prefix[r] |= 1u << bit; cand[r] = c; }
                else              { need[r] -= c; cand[r] -= c; }
                if (cand[r] == need[r]) { done |= 1u << r; ebit[r] = bit; }
            }
        }
        if (done == 15u) break;
    }
    #pragma unroll
    for (int r = 0; r < 4; ++r) {
        unsigned key;
        if (done & (1u << r)) {
            unsigned mn = 0xFFFFFFFFu;
            #pragma unroll
            for (int j = 0; j < 4; ++j) {
                bool match = (((keys[r][j] ^ prefix[r]) >> ebit[r]) == 0);
                unsigned cand_k = match ? keys[r][j] : 0xFFFFFFFFu;
                mn = cand_k < mn ? cand_k : mn;
            }
            key = __reduce_min_sync(0xffffffffu, mn);
        } else {
            key = prefix[r];
        }
        unsigned u = (key & 0x80000000u) ? (key ^ 0x80000000u) : ~key;
        thr[r] = __uint_as_float(u);
    }
}

// ---------------- q/k projection body (256-thread group, 4x4 FFMA2) ----------
__device__ __forceinline__ void proj_qk_body(
    const float* __restrict__ X, const float* __restrict__ Wm,
    const float* __restrict__ bias, float* __restrict__ Y,
    int b, int p0, float* sm, int t)
{
    float* Ws = sm;            // [32][34]
    float* Xs = sm + 32 * 34;  // [128 phys(p)][34]
    const int tx = t & 31, ty = t >> 5;
    const float* Xb = X + (size_t)b * C_ * HW_ + p0;

    u64 acc[4][4] = {};
    for (int kc = 0; kc < C_; kc += 32) {
        #pragma unroll
        for (int i = 0; i < 4; ++i) {
            int idx = t + i * 256;
            int o = idx >> 5, c = idx & 31;
            Ws[o * 34 + c] = Wm[o * C_ + kc + c];
        }
        #pragma unroll
        for (int i = 0; i < 4; ++i) {
            int idx = t + i * 256;
            int c = idx >> 5, p4 = idx & 31;
            float4 xv = *(const float4*)(Xb + (size_t)(kc + c) * HW_ + p4 * 4);
            Xs[(0 * 32 + p4) * 34 + c] = xv.x;
            Xs[(1 * 32 + p4) * 34 + c] = xv.y;
            Xs[(2 * 32 + p4) * 34 + c] = xv.z;
            Xs[(3 * 32 + p4) * 34 + c] = xv.w;
        }
        __syncthreads();
        #pragma unroll
        for (int cp = 0; cp < 16; ++cp) {
            u64 a2[4], b2[4];
            #pragma unroll
            for (int i = 0; i < 4; ++i)
                a2[i] = *(const u64*)&Ws[(ty * 4 + i) * 34 + 2 * cp];
            #pragma unroll
            for (int j = 0; j < 4; ++j)
                b2[j] = *(const u64*)&Xs[(j * 32 + tx) * 34 + 2 * cp];
            #pragma unroll
            for (int i = 0; i < 4; ++i)
                #pragma unroll
                for (int j = 0; j < 4; ++j)
                    fma2(acc[i][j], a2[i], b2[j]);
        }
        __syncthreads();
    }
    #pragma unroll
    for (int j = 0; j < 4; ++j) {
        float4 r;
        r.x = hadd2(acc[0][j]) + bias[ty * 4 + 0];
        r.y = hadd2(acc[1][j]) + bias[ty * 4 + 1];
        r.z = hadd2(acc[2][j]) + bias[ty * 4 + 2];
        r.w = hadd2(acc[3][j]) + bias[ty * 4 + 3];
        *(float4*)(Y + ((size_t)b * HW_ + p0 + tx * 4 + j) * CQ_ + ty * 4) = r;
    }
}

// ---------------- v projection body via mma (512 threads) --------------------
__device__ __forceinline__ void proj_v_mma_body(
    const float* __restrict__ x2, const float* __restrict__ Wv,
    const float* __restrict__ bv, int id, char* sm)
{
    const int b = id >> 8, o0 = ((id >> 7) & 1) * 128, p0 = (id & 127) * 128;
    const int t = threadIdx.x, wid = t >> 5, lane = t & 31;
    const int gid = lane >> 2, tig = lane & 3;
    const int wr = wid & 3, wc = wid >> 2;

    float acc[2][4][4] = {};
    for (int kc = 0; kc < C_; kc += 128) {
        #pragma unroll
        for (int i = 0; i < 8; ++i) {
            int idx = t + i * 512;
            int o = idx >> 5, c4 = (idx & 31) * 4;
            u64 hi, lo;
            split4(*(const float4*)(Wv + (size_t)(o0 + o) * C_ + kc + c4), hi, lo);
            *(u64*)(sm + OFF_T0 + (uint32_t)(o * KP + c4) * 2) = hi;
            *(u64*)(sm + OFF_T1 + (uint32_t)(o * KP + c4) * 2) = lo;
        }
        const float* Xb = x2 + ((size_t)b * C_ + kc) * HW_ + p0;
        #pragma unroll
        for (int i = 0; i < 8; ++i) {
            int idx = t + i * 512;
            int c4 = (idx >> 7) * 4, p = idx & 127;
            float4 xv;
            xv.x = Xb[(size_t)(c4 + 0) * HW_ + p];
            xv.y = Xb[(size_t)(c4 + 1) * HW_ + p];
            xv.z = Xb[(size_t)(c4 + 2) * HW_ + p];
            xv.w = Xb[(size_t)(c4 + 3) * HW_ + p];
            u64 hi, lo;
            split4(xv, hi, lo);
            *(u64*)(sm + OFF_T2 + (uint32_t)(p * KP + c4) * 2) = hi;
            *(u64*)(sm + OFF_T3 + (uint32_t)(p * KP + c4) * 2) = lo;
        }
        __syncthreads();
        #pragma unroll
        for (int ks = 0; ks < 8; ++ks) {
            const int k0 = ks * 16;
            unsigned aH[2][4], aL[2][4], bH[4][2], bL[4][2];
            #pragma unroll
            for (int i = 0; i < 2; ++i)
                ldfragA(sm, OFF_T0, OFF_T1, wr * 32 + i * 16 + gid, k0, tig, KP, aH[i], aL[i]);
            #pragma unroll
            for (int j = 0; j < 4; ++j)
                ldfragB(sm, OFF_T2, OFF_T3, wc * 32 + j * 8 + gid, k0, tig, KP, bH[j], bL[j]);
            #pragma unroll
            for (int i = 0; i < 2; ++i)
                #pragma unroll
                for (int j = 0; j < 4; ++j) {
                    mma16816(acc[i][j], aH[i], bH[j]);
                    mma16816(acc[i][j], aH[i], bL[j]);
                    mma16816(acc[i][j], aL[i], bH[j]);
                }
        }
        __syncthreads();
    }
    float* stage = (float*)sm;     // [128 o][132 p]
    #pragma unroll
    for (int i = 0; i < 2; ++i)
        #pragma unroll
        for (int j = 0; j < 4; ++j) {
            int row = wr * 32 + i * 16 + gid;
            int col = wc * 32 + j * 8 + tig * 2;
            *(float2*)&stage[row * 132 + col]       = make_float2(acc[i][j][0], acc[i][j][1]);
            *(float2*)&stage[(row + 8) * 132 + col] = make_float2(acc[i][j][2], acc[i][j][3]);
        }
    __syncthreads();
    #pragma unroll
    for (int i = 0; i < 8; ++i) {
        int idx = t + i * 512;
        int o = idx >> 5, p4 = (idx & 31) * 4;
        float bvv = bv[o0 + o];
        float2 u2 = *(float2*)&stage[o * 132 + p4];
        float2 w2 = *(float2*)&stage[o * 132 + p4 + 2];
        *(float4*)(g_v + ((size_t)b * C_ + o0 + o) * HW_ + p0 + p4) =
            make_float4(u2.x + bvv, u2.y + bvv, w2.x + bvv, w2.y + bvv);
    }
}

// ---------------- K1: ALL projections fused (512 threads) --------------------
// [0,2048): v (mma). [2048,2560): q. [2560,3072): k. qk blocks = 2x256 groups.
__global__ void __launch_bounds__(512) k1_proj(
    const float* __restrict__ x1, const float* __restrict__ x2,
    const float* __restrict__ Wq, const float* __restrict__ bq,
    const float* __restrict__ Wk, const float* __restrict__ bk,
    const float* __restrict__ Wv, const float* __restrict__ bv)
{
    extern __shared__ __align__(16) char smc[];
    const int id = blockIdx.x;
    if (id < 2048) {
        proj_v_mma_body(x2, Wv, bv, id, smc);
    } else {
        const int grp = threadIdx.x >> 8, t2 = threadIdx.x & 255;
        float* smf = (float*)smc + grp * (32 * 34 + 128 * 34);
        if (id < 2560) {
            int r = id - 2048;
            proj_qk_body(x1, Wq, bq, g_qc, r >> 6, ((r & 63) * 2 + grp) * 128, smf, t2);
        } else {
            int r = id - 2560;
            proj_qk_body(x2, Wk, bk, g_kc, r >> 6, ((r & 63) * 2 + grp) * 128, smf, t2);
        }
    }
}

// ---------------- QK score tile via mma: D[128 r][128 c] ---------------------
// Fills Q/K bf16-split tiles from q/k rows (32 c each), does 2 ksteps x 3 passes.
// Result left in acc; caller stages into Es.
__device__ __forceinline__ void qk_mma(
    const float* __restrict__ qb, const float* __restrict__ kb, size_t rowstride,
    char* sm, float acc[2][4][4])
{
    const int t = threadIdx.x, wid = t >> 5, lane = t & 31;
    const int gid = lane >> 2, tig = lane & 3;
    const int wr = wid & 3, wc = wid >> 2;
    #pragma unroll
    for (int i = 0; i < 2; ++i) {
        int idx = t + i * 512;                 // 1024 float4s per tensor
        int r = idx >> 3, c4 = (idx & 7) * 4;
        size_t off = (size_t)r * rowstride + c4;
        uint32_t so = (uint32_t)(r * KQ + c4) * 2;
        u64 hi, lo;
        split4(*(const float4*)(qb + off), hi, lo);
        *(u64*)(sm + OFF_QHI + so) = hi;
        *(u64*)(sm + OFF_QLO + so) = lo;
        split4(*(const float4*)(kb + off), hi, lo);
        *(u64*)(sm + OFF_KHI + so) = hi;
        *(u64*)(sm + OFF_KLO + so) = lo;
    }
    __syncthreads();
    #pragma unroll
    for (int ks = 0; ks < 2; ++ks) {
        const int k0 = ks * 16;
        unsigned aH[2][4], aL[2][4], bH[4][2], bL[4][2];
        #pragma unroll
        for (int i = 0; i < 2; ++i)
            ldfragA(sm, OFF_QHI, OFF_QLO, wr * 32 + i * 16 + gid, k0, tig, KQ, aH[i], aL[i]);
        #pragma unroll
        for (int j = 0; j < 4; ++j)
            ldfragB(sm, OFF_KHI, OFF_KLO, wc * 32 + j * 8 + gid, k0, tig, KQ, bH[j], bL[j]);
        #pragma unroll
        for (int i = 0; i < 2; ++i)
            #pragma unroll
            for (int j = 0; j < 4; ++j) {
                mma16816(acc[i][j], aH[i], bH[j]);
                mma16816(acc[i][j], aH[i], bL[j]);
                mma16816(acc[i][j], aL[i], bH[j]);
            }
    }
    __syncthreads();   // tiles dead; Es stage may overwrite
}

// ---------------- eH body (512 threads, mma) ----------------------------------
__device__ __forceinline__ void eH_body(int w, int b, char* sm)
{
    const int t = threadIdx.x, wid5 = t >> 5, lane = t & 31;
    const int gid = lane >> 2, tig = lane & 3;
    const int wr = wid5 & 3, wc = wid5 >> 2;
    float acc[2][4][4] = {};
    qk_mma(g_qc + ((size_t)b * HW_ + w) * CQ_,
           g_kc + ((size_t)b * HW_ + w) * CQ_,
           (size_t)W_ * CQ_, sm, acc);
    float* Es = (float*)sm;  // [128][132]
    #pragma unroll
    for (int i = 0; i < 2; ++i)
        #pragma unroll
        for (int j = 0; j < 4; ++j) {
            int row = wr * 32 + i * 16 + gid;
            int col = wc * 32 + j * 8 + tig * 2;
            Es[row * 132 + col]           = (row == col)         ? NEGF : acc[i][j][0];
            Es[row * 132 + col + 1]       = (row == col + 1)     ? NEGF : acc[i][j][1];
            Es[(row + 8) * 132 + col]     = (row + 8 == col)     ? NEGF : acc[i][j][2];
            Es[(row + 8) * 132 + col + 1] = (row + 8 == col + 1) ? NEGF : acc[i][j][3];
        }
    __syncthreads();
    #pragma unroll
    for (int grp = 0; grp < 2; ++grp) {
        float v[4][4];
        int rr[4];
        #pragma unroll
        for (int s = 0; s < 4; ++s) {
            rr[s] = wid5 + 16 * (grp * 4 + s);
            float4 x = *(const float4*)&Es[rr[s] * 132 + lane * 4];
            v[s][0] = x.x; v[s][1] = x.y; v[s][2] = x.z; v[s][3] = x.w;
        }
        float thr[4];
        topk64x4(v, thr);
        #pragma unroll
        for (int s = 0; s < 4; ++s) {
            float4 o;
            o.x = v[s][0] >= thr[s] ? v[s][0] : NEGF;
            o.y = v[s][1] >= thr[s] ? v[s][1] : NEGF;
            o.z = v[s][2] >= thr[s] ? v[s][2] : NEGF;
            o.w = v[s][3] >= thr[s] ? v[s][3] : NEGF;
            *(float4*)(g_att + (((size_t)b * H_ + rr[s]) * W_ + w) * 256 + lane * 4) = o;
        }
    }
}

// ---------------- transpose body: 64x64 tile, 512 threads --------------------
__device__ __forceinline__ void transpose_body(int n, int w0, int h0, float* sm)
{
    float* tile = sm;
    const float* s = g_v  + (size_t)n * HW_;
    float*       d = g_vt + (size_t)n * HW_;
    const int t = threadIdx.x;
    const int col = t & 63, rg = t >> 6;
    #pragma unroll
    for (int i = 0; i < 8; ++i) {
        int row = rg + i * 8;
        tile[row * 65 + col] = s[(size_t)(h0 + row) * W_ + w0 + col];
    }
    __syncthreads();
    #pragma unroll
    for (int i = 0; i < 8; ++i) {
        int row = rg + i * 8;
        d[(size_t)(w0 + row) * H_ + h0 + col] = tile[col * 65 + row];
    }
}

// ---------------- K2: eH + v-transpose fused ----------------------------------
__global__ void __launch_bounds__(512) k2_eH_tr()
{
    extern __shared__ __align__(16) char smc[];
    const int id = blockIdx.x;
    if (id < 1024) {
        eH_body(id & 127, id >> 7, smc);
    } else {
        int r = id - 1024;
        transpose_body(r >> 2, (r & 1) * 64, ((r >> 1) & 1) * 64, (float*)smc);
    }
}

// ---------------- K3: eW (mma) + joint softmax --------------------------------
__global__ void __launch_bounds__(512) k3_eW_softmax()
{
    extern __shared__ __align__(16) char smc[];
    const int h = blockIdx.x & 127, b = blockIdx.x >> 7;
    const int t = threadIdx.x, wid5 = t >> 5, lane = t & 31;
    const int gid = lane >> 2, tig = lane & 3;
    const int wr = wid5 & 3, wc = wid5 >> 2;
    float acc[2][4][4] = {};
    qk_mma(g_qc + ((size_t)b * HW_ + (size_t)h * W_) * CQ_,
           g_kc + ((size_t)b * HW_ + (size_t)h * W_) * CQ_,
           (size_t)CQ_, smc, acc);
    float* Es = (float*)smc;  // [128][132]
    #pragma unroll
    for (int i = 0; i < 2; ++i)
        #pragma unroll
        for (int j = 0; j < 4; ++j) {
            int row = wr * 32 + i * 16 + gid;
            int col = wc * 32 + j * 8 + tig * 2;
            *(float2*)&Es[row * 132 + col]       = make_float2(acc[i][j][0], acc[i][j][1]);
            *(float2*)&Es[(row + 8) * 132 + col] = make_float2(acc[i][j][2], acc[i][j][3]);
        }
    __syncthreads();
    #pragma unroll
    for (int grp = 0; grp < 2; ++grp) {
        float wv[4][4];
        int rr[4];
        #pragma unroll
        for (int s = 0; s < 4; ++s) {
            rr[s] = wid5 + 16 * (grp * 4 + s);
            float4 x = *(const float4*)&Es[rr[s] * 132 + lane * 4];
            wv[s][0] = x.x; wv[s][1] = x.y; wv[s][2] = x.z; wv[s][3] = x.w;
        }
        float thr[4];
        topk64x4(wv, thr);
        float hv[4][4];
        #pragma unroll
        for (int s = 0; s < 4; ++s) {
            #pragma unroll
            for (int j = 0; j < 4; ++j)
                wv[s][j] = (wv[s][j] >= thr[s]) ? wv[s][j] : NEGF;
            float4 x = *(const float4*)(g_att + (((size_t)b * H_ + h) * W_ + rr[s]) * 256 + lane * 4);
            hv[s][0] = x.x; hv[s][1] = x.y; hv[s][2] = x.z; hv[s][3] = x.w;
        }
        float m[4];
        #pragma unroll
        for (int s = 0; s < 4; ++s) {
            m[s] = NEGF;
            #pragma unroll
            for (int j = 0; j < 4; ++j) m[s] = fmaxf(m[s], fmaxf(wv[s][j], hv[s][j]));
        }
        #pragma unroll
        for (int off = 16; off; off >>= 1)
            #pragma unroll
            for (int s = 0; s < 4; ++s)
                m[s] = fmaxf(m[s], __shfl_xor_sync(0xffffffffu, m[s], off));
        float ph[4][4], pw[4][4], sum[4];
        #pragma unroll
        for (int s = 0; s < 4; ++s) {
            sum[s] = 0.f;
            #pragma unroll
            for (int j = 0; j < 4; ++j) {
                ph[s][j] = __expf(hv[s][j] - m[s]);
                pw[s][j] = __expf(wv[s][j] - m[s]);
                sum[s] += ph[s][j] + pw[s][j];
            }
        }
        #pragma unroll
        for (int off = 16; off; off >>= 1)
            #pragma unroll
            for (int s = 0; s < 4; ++s)
                sum[s] += __shfl_xor_sync(0xffffffffu, sum[s], off);
        #pragma unroll
        for (int s = 0; s < 4; ++s) {
            float inv = 1.0f / sum[s];
            float* arow = g_att + (((size_t)b * H_ + h) * W_ + rr[s]) * 256;
            *(float4*)(arow + lane * 4) =
                make_float4(ph[s][0]*inv, ph[s][1]*inv, ph[s][2]*inv, ph[s][3]*inv);
            *(float4*)(arow + 128 + lane * 4) =
                make_float4(pw[s][0]*inv, pw[s][1]*inv, pw[s][2]*inv, pw[s][3]*inv);
        }
    }
}

// ---------------- K4: AV GEMM via mma.sync (512 threads) ---------------------
template<bool HSIDE>
__device__ __forceinline__ void av_mma_body(int c0, int p, int b, char* sm)
{
    const int t = threadIdx.x, wid = t >> 5, lane = t & 31;
    const int gid = lane >> 2, tig = lane & 3;
    const int wr = wid & 3, wc = wid >> 2;

    const float* vbase = HSIDE ? g_vt + (((size_t)b * C_ + c0) * W_ + p) * H_
                               : g_v  + (((size_t)b * C_ + c0) * H_ + p) * W_;
    const float* abase = HSIDE ? g_att + ((size_t)b * HW_ + p) * 256
                               : g_att + (((size_t)b * H_ + p) * W_) * 256 + 128;
    const size_t astride = HSIDE ? (size_t)W_ * 256 : 256;

    #pragma unroll
    for (int i = 0; i < 8; ++i) {
        int idx = t + i * 512;
        int r = idx >> 5, g4 = (idx & 31) * 4;
        uint32_t so = (uint32_t)(r * KP + g4) * 2;
        u64 hi, lo;
        float4 v = *(const float4*)(vbase + (size_t)r * HW_ + g4);
        split4(v, hi, lo);
        *(u64*)(sm + OFF_T0 + so) = hi;
        *(u64*)(sm + OFF_T1 + so) = lo;
        float4 a = *(const float4*)(abase + (size_t)r * astride + g4);
        split4(a, hi, lo);
        *(u64*)(sm + OFF_T2 + so) = hi;
        *(u64*)(sm + OFF_T3 + so) = lo;
    }
    __syncthreads();

    float acc[2][4][4] = {};
    #pragma unroll
    for (int ks = 0; ks < 8; ++ks) {
        const int k0 = ks * 16;
        unsigned aH[2][4], aL[2][4], bH[4][2], bL[4][2];
        #pragma unroll
        for (int i = 0; i < 2; ++i)
            ldfragA(sm, OFF_T0, OFF_T1, wr * 32 + i * 16 + gid, k0, tig, KP, aH[i], aL[i]);
        #pragma unroll
        for (int j = 0; j < 4; ++j)
            ldfragB(sm, OFF_T2, OFF_T3, wc * 32 + j * 8 + gid, k0, tig, KP, bH[j], bL[j]);
        #pragma unroll
        for (int i = 0; i < 2; ++i)
            #pragma unroll
            for (int j = 0; j < 4; ++j) {
                mma16816(acc[i][j], aH[i], bH[j]);
                mma16816(acc[i][j], aH[i], bL[j]);
                mma16816(acc[i][j], aL[i], bH[j]);
            }
    }
    __syncthreads();

    float* stage = (float*)sm;   // [128][132]
    #pragma unroll
    for (int i = 0; i < 2; ++i)
        #pragma unroll
        for (int j = 0; j < 4; ++j) {
            int row = wr * 32 + i * 16 + gid;
            int col = wc * 32 + j * 8 + tig * 2;
            *(float2*)&stage[row * 132 + col]       = make_float2(acc[i][j][0], acc[i][j][1]);
            *(float2*)&stage[(row + 8) * 132 + col] = make_float2(acc[i][j][2], acc[i][j][3]);
        }
    __syncthreads();

    float* dstbase = HSIDE ? g_oht + (((size_t)b * C_ + c0) * W_ + p) * H_
                           : g_ow  + (((size_t)b * C_ + c0) * H_ + p) * W_;
    #pragma unroll
    for (int i = 0; i < 8; ++i) {
        int idx = t + i * 512;
        int r = idx >> 5, x4 = (idx & 31) * 4;
        float2 u2 = *(float2*)&stage[r * 132 + x4];
        float2 w2 = *(float2*)&stage[r * 132 + x4 + 2];
        *(float4*)(dstbase + (size_t)r * HW_ + x4) = make_float4(u2.x, u2.y, w2.x, w2.y);
    }
}

__global__ void __launch_bounds__(512) k4_out()
{
    extern __shared__ __align__(16) char smc[];
    int id = blockIdx.x;
    if (id < 2048) {
        av_mma_body<true >((id & 1) * 128, (id >> 1) & 127, id >> 8, smc);
    } else {
        id -= 2048;
        av_mma_body<false>((id & 1) * 128, (id >> 1) & 127, id >> 8, smc);
    }
}

// ---------------- K5: out = gamma*(outH^T + outW) + x1 -----------------------
__global__ void __launch_bounds__(256) k5_combine(
    const float* __restrict__ x1, const float* __restrict__ gamma,
    float* __restrict__ out)
{
    __shared__ float tile[32][33];
    const size_t n = blockIdx.z;
    const float* oht = g_oht + n * HW_;
    const float* ow  = g_ow  + n * HW_;
    const float* x   = x1    + n * HW_;
    float*       o   = out   + n * HW_;
    const int w0 = blockIdx.x * 32, h0 = blockIdx.y * 32;
    const int tx = threadIdx.x, ty = threadIdx.y;
    #pragma unroll
    for (int i = ty; i < 32; i += 8)
        tile[i][tx] = oht[(size_t)(w0 + i) * H_ + h0 + tx];
    __syncthreads();
    const float gm = gamma[0];
    #pragma unroll
    for (int i = ty; i < 32; i += 8) {
        size_t idx = (size_t)(h0 + i) * W_ + w0 + tx;
        o[idx] = gm * (tile[tx][i] + ow[idx]) + x[idx];
    }
}

// ---------------- launch ------------------------------------------------------
extern "C" void kernel_launch(void* const* d_in, const int* in_sizes, int n_in,
                              void* d_out, int out_size)
{
    (void)in_sizes; (void)n_in; (void)out_size;
    const float* x1    = (const float*)d_in[0];
    const float* x2    = (const float*)d_in[1];
    const float* Wq    = (const float*)d_in[2];
    const float* bq    = (const float*)d_in[3];
    const float* Wk    = (const float*)d_in[4];
    const float* bk    = (const float*)d_in[5];
    const float* Wv    = (const float*)d_in[6];
    const float* bv    = (const float*)d_in[7];
    const float* gamma = (const float*)d_in[8];
    float* out = (float*)d_out;

    cudaFuncSetAttribute(k1_proj,       cudaFuncAttributeMaxDynamicSharedMemorySize, SMEM_MMA);
    cudaFuncSetAttribute(k2_eH_tr,      cudaFuncAttributeMaxDynamicSharedMemorySize, SMEM_E);
    cudaFuncSetAttribute(k3_eW_softmax, cudaFuncAttributeMaxDynamicSharedMemorySize, SMEM_E);
    cudaFuncSetAttribute(k4_out,        cudaFuncAttributeMaxDynamicSharedMemorySize, SMEM_MMA);

    k1_proj      <<<3072, 512, SMEM_MMA>>>(x1, x2, Wq, bq, Wk, bk, Wv, bv);
    k2_eH_tr     <<<1024 + 8192, 512, SMEM_E>>>();
    k3_eW_softmax<<<1024, 512, SMEM_E>>>();
    k4_out       <<<4096, 512, SMEM_MMA>>>();
    k5_combine   <<<dim3(4, 4, B_*C_), dim3(32, 8)>>>(x1, gamma, out);
}

// round 14
// speedup vs baseline: 1.0279x; 1.0279x over previous
#include <cuda_runtime.h>
#include <cuda_bf16.h>
#include <cstdint>

#define B_   8
#define C_   256
#define CQ_  32
#define H_   128
#define W_   128
#define HW_  (H_*W_)

typedef unsigned long long u64;

// ---------------- scratch ----------------------------------------------------
__device__ float g_qc [(size_t)B_*HW_*CQ_];   // [b, p, c]
__device__ float g_kc [(size_t)B_*HW_*CQ_];   // [b, p, c]
__device__ float g_v  [(size_t)B_*C_*HW_];    // [b, c, h, w]
__device__ float g_vt [(size_t)B_*C_*HW_];    // [b, c, w, h]
__device__ float g_att[(size_t)B_*H_*W_*256]; // [b,h,w, 0:128=H, 128:256=W]
__device__ float g_oht[(size_t)B_*C_*HW_];    // outH transposed: [b,c,w,h]
__device__ float g_ow [(size_t)B_*C_*HW_];    // outW: [b,c,h,w]

#define NEGF (__int_as_float(0xff800000))

// ---------------- packed fp32x2 helpers --------------------------------------
__device__ __forceinline__ void fma2(u64& d, u64 a, u64 b) {
    asm("fma.rn.f32x2 %0, %1, %2, %0;" : "+l"(d) : "l"(a), "l"(b));
}
__device__ __forceinline__ float hadd2(u64 v) {
    float lo, hi;
    asm("mov.b64 {%0,%1}, %2;" : "=f"(lo), "=f"(hi) : "l"(v));
    return lo + hi;
}
__device__ __forceinline__ void st2x(float* p, float4 v) {
    *(float2*)p       = make_float2(v.x, v.y);
    *(float2*)(p + 2) = make_float2(v.z, v.w);
}

// ---------------- bf16 split helpers ------------------------------------------
__device__ __forceinline__ u64 pack4bf(__nv_bfloat16 a, __nv_bfloat16 b,
                                        __nv_bfloat16 c, __nv_bfloat16 d) {
    unsigned lo = ((unsigned)__bfloat16_as_ushort(b) << 16) | __bfloat16_as_ushort(a);
    unsigned hi = ((unsigned)__bfloat16_as_ushort(d) << 16) | __bfloat16_as_ushort(c);
    return (u64)lo | ((u64)hi << 32);
}
__device__ __forceinline__ void split4(float4 v, u64& hi, u64& lo) {
    __nv_bfloat16 h0 = __float2bfloat16(v.x), h1 = __float2bfloat16(v.y);
    __nv_bfloat16 h2 = __float2bfloat16(v.z), h3 = __float2bfloat16(v.w);
    __nv_bfloat16 l0 = __float2bfloat16(v.x - __bfloat162float(h0));
    __nv_bfloat16 l1 = __float2bfloat16(v.y - __bfloat162float(h1));
    __nv_bfloat16 l2 = __float2bfloat16(v.z - __bfloat162float(h2));
    __nv_bfloat16 l3 = __float2bfloat16(v.w - __bfloat162float(h3));
    hi = pack4bf(h0, h1, h2, h3);
    lo = pack4bf(l0, l1, l2, l3);
}
__device__ __forceinline__ void mma16816(float c[4], const unsigned a[4], const unsigned b[2]) {
    asm volatile(
        "mma.sync.aligned.m16n8k16.row.col.f32.bf16.bf16.f32 "
        "{%0,%1,%2,%3}, {%4,%5,%6,%7}, {%8,%9}, {%0,%1,%2,%3};"
        : "+f"(c[0]), "+f"(c[1]), "+f"(c[2]), "+f"(c[3])
        : "r"(a[0]), "r"(a[1]), "r"(a[2]), "r"(a[3]), "r"(b[0]), "r"(b[1]));
}

#define KP    136                         // K=128 pitch (bf16)
#define KQ    40                          // K=32 pitch (bf16)
#define T64   (64 * KP * 2)               // 17408
#define T128  (128 * KP * 2)              // 34816
#define QTB   (128 * KQ * 2)              // 10240

// k4 (c-tile 64): V hi/lo (64 rows), A hi/lo (128 rows)
#define K4_VHI 0
#define K4_VLO (T64)
#define K4_AHI (2 * T64)
#define K4_ALO (2 * T64 + T128)
#define SMEM_K4 (2 * T64 + 2 * T128)      // 104448

// k1v (p-tile 64): W hi/lo (128 rows), X hi/lo (64 rows)
#define K1_WHI 0
#define K1_WLO (T128)
#define K1_XHI (2 * T128)
#define K1_XLO (2 * T128 + T64)
#define SMEM_K1 (2 * T128 + 2 * T64)      // 104448

// eH/eW QK tiles
#define OFF_QHI 0
#define OFF_QLO (QTB)
#define OFF_KHI (2 * QTB)
#define OFF_KLO (3 * QTB)
#define SMEM_E  (128 * 132 * 4)           // 67584

__device__ __forceinline__ void ldfragA(const char* sm, int hiOff, int loOff,
                                        int rb, int k0, int tig, int kp,
                                        unsigned aH[4], unsigned aL[4]) {
    uint32_t o0 = (uint32_t)(rb * kp + k0 + tig * 2) * 2;
    uint32_t o1 = o0 + 8 * kp * 2;
    aH[0] = *(const unsigned*)(sm + hiOff + o0);
    aH[1] = *(const unsigned*)(sm + hiOff + o1);
    aH[2] = *(const unsigned*)(sm + hiOff + o0 + 16);
    aH[3] = *(const unsigned*)(sm + hiOff + o1 + 16);
    aL[0] = *(const unsigned*)(sm + loOff + o0);
    aL[1] = *(const unsigned*)(sm + loOff + o1);
    aL[2] = *(const unsigned*)(sm + loOff + o0 + 16);
    aL[3] = *(const unsigned*)(sm + loOff + o1 + 16);
}
__device__ __forceinline__ void ldfragB(const char* sm, int hiOff, int loOff,
                                        int xb, int k0, int tig, int kp,
                                        unsigned bH[2], unsigned bL[2]) {
    uint32_t o0 = (uint32_t)(xb * kp + k0 + tig * 2) * 2;
    bH[0] = *(const unsigned*)(sm + hiOff + o0);
    bH[1] = *(const unsigned*)(sm + hiOff + o0 + 16);
    bL[0] = *(const unsigned*)(sm + loOff + o0);
    bL[1] = *(const unsigned*)(sm + loOff + o0 + 16);
}

// ---------------- exact 64th-largest, 4 rows, packed counts + early exit -----
__device__ __forceinline__ void topk64x4(const float v[4][4], float thr[4])
{
    unsigned keys[4][4];
    #pragma unroll
    for (int r = 0; r < 4; ++r)
        #pragma unroll
        for (int j = 0; j < 4; ++j) {
            unsigned u = __float_as_uint(v[r][j]);
            keys[r][j] = (u & 0x80000000u) ? ~u : (u | 0x80000000u);
        }
    unsigned prefix[4] = {0, 0, 0, 0};
    unsigned need[4]   = {64, 64, 64, 64};
    unsigned cand[4]   = {128, 128, 128, 128};
    int      ebit[4]   = {0, 0, 0, 0};
    unsigned done = 0;

    for (int bit = 31; bit >= 0; --bit) {
        unsigned packed = 0;
        #pragma unroll
        for (int r = 0; r < 4; ++r) {
            if (!(done & (1u << r))) {
                unsigned want = (prefix[r] >> bit) | 1u;
                unsigned c = 0;
                #pragma unroll
                for (int j = 0; j < 4; ++j)
                    c += (unsigned)((keys[r][j] >> bit) == want);
                packed += c << (8 * r);
            }
        }
        packed = __reduce_add_sync(0xffffffffu, packed);
        #pragma unroll
        for (int r = 0; r < 4; ++r) {
            if (!(done & (1u << r))) {
                unsigned c = (packed >> (8 * r)) & 255u;
                if (c >= need[r]) { prefix[r] |= 1u << bit; cand[r] = c; }
                else              { need[r] -= c; cand[r] -= c; }
                if (cand[r] == need[r]) { done |= 1u << r; ebit[r] = bit; }
            }
        }
        if (done == 15u) break;
    }
    #pragma unroll
    for (int r = 0; r < 4; ++r) {
        unsigned key;
        if (done & (1u << r)) {
            unsigned mn = 0xFFFFFFFFu;
            #pragma unroll
            for (int j = 0; j < 4; ++j) {
                bool match = (((keys[r][j] ^ prefix[r]) >> ebit[r]) == 0);
                unsigned cand_k = match ? keys[r][j] : 0xFFFFFFFFu;
                mn = cand_k < mn ? cand_k : mn;
            }
            key = __reduce_min_sync(0xffffffffu, mn);
        } else {
            key = prefix[r];
        }
        unsigned u = (key & 0x80000000u) ? (key ^ 0x80000000u) : ~key;
        thr[r] = __uint_as_float(u);
    }
}

// ---------------- K0: q/k projections (256 threads, 4x4 FFMA2) ---------------
__device__ __forceinline__ void proj_qk_body(
    const float* __restrict__ X, const float* __restrict__ Wm,
    const float* __restrict__ bias, float* __restrict__ Y,
    int b, int p0, float* sm)
{
    float* Ws = sm;            // [32][34]
    float* Xs = sm + 32 * 34;  // [128 phys(p)][34]
    const int t  = threadIdx.x;
    const int tx = t & 31, ty = t >> 5;
    const float* Xb = X + (size_t)b * C_ * HW_ + p0;

    u64 acc[4][4] = {};
    for (int kc = 0; kc < C_; kc += 32) {
        #pragma unroll
        for (int i = 0; i < 4; ++i) {
            int idx = t + i * 256;
            int o = idx >> 5, c = idx & 31;
            Ws[o * 34 + c] = Wm[o * C_ + kc + c];
        }
        #pragma unroll
        for (int i = 0; i < 4; ++i) {
            int idx = t + i * 256;
            int c = idx >> 5, p4 = idx & 31;
            float4 xv = *(const float4*)(Xb + (size_t)(kc + c) * HW_ + p4 * 4);
            Xs[(0 * 32 + p4) * 34 + c] = xv.x;
            Xs[(1 * 32 + p4) * 34 + c] = xv.y;
            Xs[(2 * 32 + p4) * 34 + c] = xv.z;
            Xs[(3 * 32 + p4) * 34 + c] = xv.w;
        }
        __syncthreads();
        #pragma unroll
        for (int cp = 0; cp < 16; ++cp) {
            u64 a2[4], b2[4];
            #pragma unroll
            for (int i = 0; i < 4; ++i)
                a2[i] = *(const u64*)&Ws[(ty * 4 + i) * 34 + 2 * cp];
            #pragma unroll
            for (int j = 0; j < 4; ++j)
                b2[j] = *(const u64*)&Xs[(j * 32 + tx) * 34 + 2 * cp];
            #pragma unroll
            for (int i = 0; i < 4; ++i)
                #pragma unroll
                for (int j = 0; j < 4; ++j)
                    fma2(acc[i][j], a2[i], b2[j]);
        }
        __syncthreads();
    }
    #pragma unroll
    for (int j = 0; j < 4; ++j) {
        float4 r;
        r.x = hadd2(acc[0][j]) + bias[ty * 4 + 0];
        r.y = hadd2(acc[1][j]) + bias[ty * 4 + 1];
        r.z = hadd2(acc[2][j]) + bias[ty * 4 + 2];
        r.w = hadd2(acc[3][j]) + bias[ty * 4 + 3];
        *(float4*)(Y + ((size_t)b * HW_ + p0 + tx * 4 + j) * CQ_ + ty * 4) = r;
    }
}

__global__ void __launch_bounds__(256) k0_qk(
    const float* __restrict__ x1, const float* __restrict__ x2,
    const float* __restrict__ Wq, const float* __restrict__ bq,
    const float* __restrict__ Wk, const float* __restrict__ bk)
{
    extern __shared__ __align__(16) float sm[];
    const int id = blockIdx.x;
    if (id < 1024) proj_qk_body(x1, Wq, bq, g_qc, id >> 7, (id & 127) * 128, sm);
    else { int r = id - 1024; proj_qk_body(x2, Wk, bk, g_kc, r >> 7, (r & 127) * 128, sm); }
}

// ---------------- K1: v projection via mma, p-tile 64, 2 CTAs/SM -------------
__global__ void __launch_bounds__(512, 2) k1v_proj(
    const float* __restrict__ x2, const float* __restrict__ Wv,
    const float* __restrict__ bv)
{
    extern __shared__ __align__(16) char smc[];
    char* sm = smc;
    const int id = blockIdx.x;
    const int b = id >> 9, o0 = ((id >> 8) & 1) * 128, p0 = (id & 255) * 64;
    const int t = threadIdx.x, wid = t >> 5, lane = t & 31;
    const int gid = lane >> 2, tig = lane & 3;
    const int wr = wid & 3, wc = wid >> 2;   // warp tile: 32 o x 16 p

    float acc[2][2][4] = {};
    for (int kc = 0; kc < C_; kc += 128) {
        #pragma unroll
        for (int i = 0; i < 8; ++i) {                    // W: 4096 float4
            int idx = t + i * 512;
            int o = idx >> 5, c4 = (idx & 31) * 4;
            u64 hi, lo;
            split4(*(const float4*)(Wv + (size_t)(o0 + o) * C_ + kc + c4), hi, lo);
            *(u64*)(sm + K1_WHI + (uint32_t)(o * KP + c4) * 2) = hi;
            *(u64*)(sm + K1_WLO + (uint32_t)(o * KP + c4) * 2) = lo;
        }
        const float* Xb = x2 + ((size_t)b * C_ + kc) * HW_ + p0;
        #pragma unroll
        for (int i = 0; i < 4; ++i) {                    // X: 2048 packs of 4c
            int idx = t + i * 512;
            int c4 = (idx >> 6) * 4, p = idx & 63;
            float4 xv;
            xv.x = Xb[(size_t)(c4 + 0) * HW_ + p];
            xv.y = Xb[(size_t)(c4 + 1) * HW_ + p];
            xv.z = Xb[(size_t)(c4 + 2) * HW_ + p];
            xv.w = Xb[(size_t)(c4 + 3) * HW_ + p];
            u64 hi, lo;
            split4(xv, hi, lo);
            *(u64*)(sm + K1_XHI + (uint32_t)(p * KP + c4) * 2) = hi;
            *(u64*)(sm + K1_XLO + (uint32_t)(p * KP + c4) * 2) = lo;
        }
        __syncthreads();
        #pragma unroll
        for (int ks = 0; ks < 8; ++ks) {
            const int k0 = ks * 16;
            unsigned aH[2][4], aL[2][4], bH[2][2], bL[2][2];
            #pragma unroll
            for (int i = 0; i < 2; ++i)
                ldfragA(sm, K1_WHI, K1_WLO, wr * 32 + i * 16 + gid, k0, tig, KP, aH[i], aL[i]);
            #pragma unroll
            for (int j = 0; j < 2; ++j)
                ldfragB(sm, K1_XHI, K1_XLO, wc * 16 + j * 8 + gid, k0, tig, KP, bH[j], bL[j]);
            #pragma unroll
            for (int i = 0; i < 2; ++i)
                #pragma unroll
                for (int j = 0; j < 2; ++j) {
                    mma16816(acc[i][j], aH[i], bH[j]);
                    mma16816(acc[i][j], aH[i], bL[j]);
                    mma16816(acc[i][j], aL[i], bH[j]);
                }
        }
        __syncthreads();
    }
    float* stage = (float*)sm;     // [128 o][68 p]
    #pragma unroll
    for (int i = 0; i < 2; ++i)
        #pragma unroll
        for (int j = 0; j < 2; ++j) {
            int row = wr * 32 + i * 16 + gid;
            int col = wc * 16 + j * 8 + tig * 2;
            *(float2*)&stage[row * 68 + col]       = make_float2(acc[i][j][0], acc[i][j][1]);
            *(float2*)&stage[(row + 8) * 68 + col] = make_float2(acc[i][j][2], acc[i][j][3]);
        }
    __syncthreads();
    #pragma unroll
    for (int i = 0; i < 4; ++i) {
        int idx = t + i * 512;                 // 2048 float4
        int o = idx >> 4, p4 = (idx & 15) * 4;
        float bvv = bv[o0 + o];
        float2 u2 = *(float2*)&stage[o * 68 + p4];
        float2 w2 = *(float2*)&stage[o * 68 + p4 + 2];
        *(float4*)(g_v + ((size_t)b * C_ + o0 + o) * HW_ + p0 + p4) =
            make_float4(u2.x + bvv, u2.y + bvv, w2.x + bvv, w2.y + bvv);
    }
}

// ---------------- QK score tile via mma ---------------------------------------
__device__ __forceinline__ void qk_mma(
    const float* __restrict__ qb, const float* __restrict__ kb, size_t rowstride,
    char* sm, float acc[2][4][4])
{
    const int t = threadIdx.x, wid = t >> 5, lane = t & 31;
    const int gid = lane >> 2, tig = lane & 3;
    const int wr = wid & 3, wc = wid >> 2;
    #pragma unroll
    for (int i = 0; i < 2; ++i) {
        int idx = t + i * 512;
        int r = idx >> 3, c4 = (idx & 7) * 4;
        size_t off = (size_t)r * rowstride + c4;
        uint32_t so = (uint32_t)(r * KQ + c4) * 2;
        u64 hi, lo;
        split4(*(const float4*)(qb + off), hi, lo);
        *(u64*)(sm + OFF_QHI + so) = hi;
        *(u64*)(sm + OFF_QLO + so) = lo;
        split4(*(const float4*)(kb + off), hi, lo);
        *(u64*)(sm + OFF_KHI + so) = hi;
        *(u64*)(sm + OFF_KLO + so) = lo;
    }
    __syncthreads();
    #pragma unroll
    for (int ks = 0; ks < 2; ++ks) {
        const int k0 = ks * 16;
        unsigned aH[2][4], aL[2][4], bH[4][2], bL[4][2];
        #pragma unroll
        for (int i = 0; i < 2; ++i)
            ldfragA(sm, OFF_QHI, OFF_QLO, wr * 32 + i * 16 + gid, k0, tig, KQ, aH[i], aL[i]);
        #pragma unroll
        for (int j = 0; j < 4; ++j)
            ldfragB(sm, OFF_KHI, OFF_KLO, wc * 32 + j * 8 + gid, k0, tig, KQ, bH[j], bL[j]);
        #pragma unroll
        for (int i = 0; i < 2; ++i)
            #pragma unroll
            for (int j = 0; j < 4; ++j) {
                mma16816(acc[i][j], aH[i], bH[j]);
                mma16816(acc[i][j], aH[i], bL[j]);
                mma16816(acc[i][j], aL[i], bH[j]);
            }
    }
    __syncthreads();
}

// ---------------- eH body (512 threads, mma) ----------------------------------
__device__ __forceinline__ void eH_body(int w, int b, char* sm)
{
    const int t = threadIdx.x, wid5 = t >> 5, lane = t & 31;
    const int gid = lane >> 2, tig = lane & 3;
    const int wr = wid5 & 3, wc = wid5 >> 2;
    float acc[2][4][4] = {};
    qk_mma(g_qc + ((size_t)b * HW_ + w) * CQ_,
           g_kc + ((size_t)b * HW_ + w) * CQ_,
           (size_t)W_ * CQ_, sm, acc);
    float* Es = (float*)sm;  // [128][132]
    #pragma unroll
    for (int i = 0; i < 2; ++i)
        #pragma unroll
        for (int j = 0; j < 4; ++j) {
            int row = wr * 32 + i * 16 + gid;
            int col = wc * 32 + j * 8 + tig * 2;
            Es[row * 132 + col]           = (row == col)         ? NEGF : acc[i][j][0];
            Es[row * 132 + col + 1]       = (row == col + 1)     ? NEGF : acc[i][j][1];
            Es[(row + 8) * 132 + col]     = (row + 8 == col)     ? NEGF : acc[i][j][2];
            Es[(row + 8) * 132 + col + 1] = (row + 8 == col + 1) ? NEGF : acc[i][j][3];
        }
    __syncthreads();
    #pragma unroll
    for (int grp = 0; grp < 2; ++grp) {
        float v[4][4];
        int rr[4];
        #pragma unroll
        for (int s = 0; s < 4; ++s) {
            rr[s] = wid5 + 16 * (grp * 4 + s);
            float4 x = *(const float4*)&Es[rr[s] * 132 + lane * 4];
            v[s][0] = x.x; v[s][1] = x.y; v[s][2] = x.z; v[s][3] = x.w;
        }
        float thr[4];
        topk64x4(v, thr);
        #pragma unroll
        for (int s = 0; s < 4; ++s) {
            float4 o;
            o.x = v[s][0] >= thr[s] ? v[s][0] : NEGF;
            o.y = v[s][1] >= thr[s] ? v[s][1] : NEGF;
            o.z = v[s][2] >= thr[s] ? v[s][2] : NEGF;
            o.w = v[s][3] >= thr[s] ? v[s][3] : NEGF;
            *(float4*)(g_att + (((size_t)b * H_ + rr[s]) * W_ + w) * 256 + lane * 4) = o;
        }
    }
}

// ---------------- transpose body: 64x64 tile, 512 threads --------------------
__device__ __forceinline__ void transpose_body(int n, int w0, int h0, float* sm)
{
    float* tile = sm;
    const float* s = g_v  + (size_t)n * HW_;
    float*       d = g_vt + (size_t)n * HW_;
    const int t = threadIdx.x;
    const int col = t & 63, rg = t >> 6;
    #pragma unroll
    for (int i = 0; i < 8; ++i) {
        int row = rg + i * 8;
        tile[row * 65 + col] = s[(size_t)(h0 + row) * W_ + w0 + col];
    }
    __syncthreads();
    #pragma unroll
    for (int i = 0; i < 8; ++i) {
        int row = rg + i * 8;
        d[(size_t)(w0 + row) * H_ + h0 + col] = tile[col * 65 + row];
    }
}

// ---------------- K2: eH + v-transpose fused ----------------------------------
__global__ void __launch_bounds__(512) k2_eH_tr()
{
    extern __shared__ __align__(16) char smc[];
    const int id = blockIdx.x;
    if (id < 1024) {
        eH_body(id & 127, id >> 7, smc);
    } else {
        int r = id - 1024;
        transpose_body(r >> 2, (r & 1) * 64, ((r >> 1) & 1) * 64, (float*)smc);
    }
}

// ---------------- K3: eW (mma) + joint softmax --------------------------------
__global__ void __launch_bounds__(512) k3_eW_softmax()
{
    extern __shared__ __align__(16) char smc[];
    const int h = blockIdx.x & 127, b = blockIdx.x >> 7;
    const int t = threadIdx.x, wid5 = t >> 5, lane = t & 31;
    const int gid = lane >> 2, tig = lane & 3;
    const int wr = wid5 & 3, wc = wid5 >> 2;
    float acc[2][4][4] = {};
    qk_mma(g_qc + ((size_t)b * HW_ + (size_t)h * W_) * CQ_,
           g_kc + ((size_t)b * HW_ + (size_t)h * W_) * CQ_,
           (size_t)CQ_, smc, acc);
    float* Es = (float*)smc;  // [128][132]
    #pragma unroll
    for (int i = 0; i < 2; ++i)
        #pragma unroll
        for (int j = 0; j < 4; ++j) {
            int row = wr * 32 + i * 16 + gid;
            int col = wc * 32 + j * 8 + tig * 2;
            *(float2*)&Es[row * 132 + col]       = make_float2(acc[i][j][0], acc[i][j][1]);
            *(float2*)&Es[(row + 8) * 132 + col] = make_float2(acc[i][j][2], acc[i][j][3]);
        }
    __syncthreads();
    #pragma unroll
    for (int grp = 0; grp < 2; ++grp) {
        float wv[4][4];
        int rr[4];
        #pragma unroll
        for (int s = 0; s < 4; ++s) {
            rr[s] = wid5 + 16 * (grp * 4 + s);
            float4 x = *(const float4*)&Es[rr[s] * 132 + lane * 4];
            wv[s][0] = x.x; wv[s][1] = x.y; wv[s][2] = x.z; wv[s][3] = x.w;
        }
        float thr[4];
        topk64x4(wv, thr);
        float hv[4][4];
        #pragma unroll
        for (int s = 0; s < 4; ++s) {
            #pragma unroll
            for (int j = 0; j < 4; ++j)
                wv[s][j] = (wv[s][j] >= thr[s]) ? wv[s][j] : NEGF;
            float4 x = *(const float4*)(g_att + (((size_t)b * H_ + h) * W_ + rr[s]) * 256 + lane * 4);
            hv[s][0] = x.x; hv[s][1] = x.y; hv[s][2] = x.z; hv[s][3] = x.w;
        }
        float m[4];
        #pragma unroll
        for (int s = 0; s < 4; ++s) {
            m[s] = NEGF;
            #pragma unroll
            for (int j = 0; j < 4; ++j) m[s] = fmaxf(m[s], fmaxf(wv[s][j], hv[s][j]));
        }
        #pragma unroll
        for (int off = 16; off; off >>= 1)
            #pragma unroll
            for (int s = 0; s < 4; ++s)
                m[s] = fmaxf(m[s], __shfl_xor_sync(0xffffffffu, m[s], off));
        float ph[4][4], pw[4][4], sum[4];
        #pragma unroll
        for (int s = 0; s < 4; ++s) {
            sum[s] = 0.f;
            #pragma unroll
            for (int j = 0; j < 4; ++j) {
                ph[s][j] = __expf(hv[s][j] - m[s]);
                pw[s][j] = __expf(wv[s][j] - m[s]);
                sum[s] += ph[s][j] + pw[s][j];
            }
        }
        #pragma unroll
        for (int off = 16; off; off >>= 1)
            #pragma unroll
            for (int s = 0; s < 4; ++s)
                sum[s] += __shfl_xor_sync(0xffffffffu, sum[s], off);
        #pragma unroll
        for (int s = 0; s < 4; ++s) {
            float inv = 1.0f / sum[s];
            float* arow = g_att + (((size_t)b * H_ + h) * W_ + rr[s]) * 256;
            *(float4*)(arow + lane * 4) =
                make_float4(ph[s][0]*inv, ph[s][1]*inv, ph[s][2]*inv, ph[s][3]*inv);
            *(float4*)(arow + 128 + lane * 4) =
                make_float4(pw[s][0]*inv, pw[s][1]*inv, pw[s][2]*inv, pw[s][3]*inv);
        }
    }
}

// ---------------- K4: AV GEMM via mma, c-tile 64, 2 CTAs/SM ------------------
template<bool HSIDE>
__device__ __forceinline__ void av_mma_body(int c0, int p, int b, char* sm)
{
    const int t = threadIdx.x, wid = t >> 5, lane = t & 31;
    const int gid = lane >> 2, tig = lane & 3;
    const int wr = wid & 3, wc = wid >> 2;   // warp tile: 16 c x 32 x

    const float* vbase = HSIDE ? g_vt + (((size_t)b * C_ + c0) * W_ + p) * H_
                               : g_v  + (((size_t)b * C_ + c0) * H_ + p) * W_;
    const float* abase = HSIDE ? g_att + ((size_t)b * HW_ + p) * 256
                               : g_att + (((size_t)b * H_ + p) * W_) * 256 + 128;
    const size_t astride = HSIDE ? (size_t)W_ * 256 : 256;

    #pragma unroll
    for (int i = 0; i < 4; ++i) {            // V: 64x128 = 2048 float4
        int idx = t + i * 512;
        int r = idx >> 5, g4 = (idx & 31) * 4;
        uint32_t so = (uint32_t)(r * KP + g4) * 2;
        u64 hi, lo;
        split4(*(const float4*)(vbase + (size_t)r * HW_ + g4), hi, lo);
        *(u64*)(sm + K4_VHI + so) = hi;
        *(u64*)(sm + K4_VLO + so) = lo;
    }
    #pragma unroll
    for (int i = 0; i < 8; ++i) {            // A: 128x128 = 4096 float4
        int idx = t + i * 512;
        int r = idx >> 5, g4 = (idx & 31) * 4;
        uint32_t so = (uint32_t)(r * KP + g4) * 2;
        u64 hi, lo;
        split4(*(const float4*)(abase + (size_t)r * astride + g4), hi, lo);
        *(u64*)(sm + K4_AHI + so) = hi;
        *(u64*)(sm + K4_ALO + so) = lo;
    }
    __syncthreads();

    float acc[4][4] = {};
    #pragma unroll
    for (int ks = 0; ks < 8; ++ks) {
        const int k0 = ks * 16;
        unsigned aH[4], aL[4], bH[4][2], bL[4][2];
        ldfragA(sm, K4_VHI, K4_VLO, wr * 16 + gid, k0, tig, KP, aH, aL);
        #pragma unroll
        for (int j = 0; j < 4; ++j)
            ldfragB(sm, K4_AHI, K4_ALO, wc * 32 + j * 8 + gid, k0, tig, KP, bH[j], bL[j]);
        #pragma unroll
        for (int j = 0; j < 4; ++j) {
            mma16816(acc[j], aH, bH[j]);
            mma16816(acc[j], aH, bL[j]);
            mma16816(acc[j], aL, bH[j]);
        }
    }
    __syncthreads();

    float* stage = (float*)sm;   // [64][132]
    #pragma unroll
    for (int j = 0; j < 4; ++j) {
        int row = wr * 16 + gid;
        int col = wc * 32 + j * 8 + tig * 2;
        *(float2*)&stage[row * 132 + col]       = make_float2(acc[j][0], acc[j][1]);
        *(float2*)&stage[(row + 8) * 132 + col] = make_float2(acc[j][2], acc[j][3]);
    }
    __syncthreads();

    float* dstbase = HSIDE ? g_oht + (((size_t)b * C_ + c0) * W_ + p) * H_
                           : g_ow  + (((size_t)b * C_ + c0) * H_ + p) * W_;
    #pragma unroll
    for (int i = 0; i < 4; ++i) {            // 64x128 = 2048 float4
        int idx = t + i * 512;
        int r = idx >> 5, x4 = (idx & 31) * 4;
        float2 u2 = *(float2*)&stage[r * 132 + x4];
        float2 w2 = *(float2*)&stage[r * 132 + x4 + 2];
        *(float4*)(dstbase + (size_t)r * HW_ + x4) = make_float4(u2.x, u2.y, w2.x, w2.y);
    }
}

__global__ void __launch_bounds__(512, 2) k4_out()
{
    extern __shared__ __align__(16) char smc[];
    int id = blockIdx.x;
    if (id < 4096) {
        av_mma_body<true >((id & 3) * 64, (id >> 2) & 127, id >> 9, smc);
    } else {
        id -= 4096;
        av_mma_body<false>((id & 3) * 64, (id >> 2) & 127, id >> 9, smc);
    }
}

// ---------------- K5: out = gamma*(outH^T + outW) + x1 -----------------------
__global__ void __launch_bounds__(256) k5_combine(
    const float* __restrict__ x1, const float* __restrict__ gamma,
    float* __restrict__ out)
{
    __shared__ float tile[32][33];
    const size_t n = blockIdx.z;
    const float* oht = g_oht + n * HW_;
    const float* ow  = g_ow  + n * HW_;
    const float* x   = x1    + n * HW_;
    float*       o   = out   + n * HW_;
    const int w0 = blockIdx.x * 32, h0 = blockIdx.y * 32;
    const int tx = threadIdx.x, ty = threadIdx.y;
    #pragma unroll
    for (int i = ty; i < 32; i += 8)
        tile[i][tx] = oht[(size_t)(w0 + i) * H_ + h0 + tx];
    __syncthreads();
    const float gm = gamma[0];
    #pragma unroll
    for (int i = ty; i < 32; i += 8) {
        size_t idx = (size_t)(h0 + i) * W_ + w0 + tx;
        o[idx] = gm * (tile[tx][i] + ow[idx]) + x[idx];
    }
}

// ---------------- launch ------------------------------------------------------
extern "C" void kernel_launch(void* const* d_in, const int* in_sizes, int n_in,
                              void* d_out, int out_size)
{
    (void)in_sizes; (void)n_in; (void)out_size;
    const float* x1    = (const float*)d_in[0];
    const float* x2    = (const float*)d_in[1];
    const float* Wq    = (const float*)d_in[2];
    const float* bq    = (const float*)d_in[3];
    const float* Wk    = (const float*)d_in[4];
    const float* bk    = (const float*)d_in[5];
    const float* Wv    = (const float*)d_in[6];
    const float* bv    = (const float*)d_in[7];
    const float* gamma = (const float*)d_in[8];
    float* out = (float*)d_out;

    const int SMEM_P = (32 * 34 + 128 * 34) * 4;        // 21760
    cudaFuncSetAttribute(k0_qk,         cudaFuncAttributeMaxDynamicSharedMemorySize, SMEM_P);
    cudaFuncSetAttribute(k1v_proj,      cudaFuncAttributeMaxDynamicSharedMemorySize, SMEM_K1);
    cudaFuncSetAttribute(k2_eH_tr,      cudaFuncAttributeMaxDynamicSharedMemorySize, SMEM_E);
    cudaFuncSetAttribute(k3_eW_softmax, cudaFuncAttributeMaxDynamicSharedMemorySize, SMEM_E);
    cudaFuncSetAttribute(k4_out,        cudaFuncAttributeMaxDynamicSharedMemorySize, SMEM_K4);

    k0_qk        <<<2048, 256, SMEM_P>>>(x1, x2, Wq, bq, Wk, bk);
    k1v_proj     <<<4096, 512, SMEM_K1>>>(x2, Wv, bv);
    k2_eH_tr     <<<1024 + 8192, 512, SMEM_E>>>();
    k3_eW_softmax<<<1024, 512, SMEM_E>>>();
    k4_out       <<<8192, 512, SMEM_K4>>>();
    k5_combine   <<<dim3(4, 4, B_*C_), dim3(32, 8)>>>(x1, gamma, out);
}

// round 15
// speedup vs baseline: 1.1570x; 1.1256x over previous
#include <cuda_runtime.h>
#include <cuda_bf16.h>
#include <cstdint>

#define B_   8
#define C_   256
#define CQ_  32
#define H_   128
#define W_   128
#define HW_  (H_*W_)

typedef unsigned long long u64;

// ---------------- scratch ----------------------------------------------------
__device__ float g_qc [(size_t)B_*HW_*CQ_];   // [b, p, c]
__device__ float g_kc [(size_t)B_*HW_*CQ_];   // [b, p, c]
__device__ float g_v  [(size_t)B_*C_*HW_];    // [b, c, h, w]
__device__ float g_vt [(size_t)B_*C_*HW_];    // [b, c, w, h]
__device__ float g_att[(size_t)B_*H_*W_*256]; // [b,h,w, 0:128=H, 128:256=W]
__device__ float g_oht[(size_t)B_*C_*HW_];    // outH transposed: [b,c,w,h]
__device__ float g_ow [(size_t)B_*C_*HW_];    // outW: [b,c,h,w]

#define NEGF (__int_as_float(0xff800000))

// ---------------- bf16 split helpers ------------------------------------------
__device__ __forceinline__ u64 pack4bf(__nv_bfloat16 a, __nv_bfloat16 b,
                                        __nv_bfloat16 c, __nv_bfloat16 d) {
    unsigned lo = ((unsigned)__bfloat16_as_ushort(b) << 16) | __bfloat16_as_ushort(a);
    unsigned hi = ((unsigned)__bfloat16_as_ushort(d) << 16) | __bfloat16_as_ushort(c);
    return (u64)lo | ((u64)hi << 32);
}
__device__ __forceinline__ void split4(float4 v, u64& hi, u64& lo) {
    __nv_bfloat16 h0 = __float2bfloat16(v.x), h1 = __float2bfloat16(v.y);
    __nv_bfloat16 h2 = __float2bfloat16(v.z), h3 = __float2bfloat16(v.w);
    __nv_bfloat16 l0 = __float2bfloat16(v.x - __bfloat162float(h0));
    __nv_bfloat16 l1 = __float2bfloat16(v.y - __bfloat162float(h1));
    __nv_bfloat16 l2 = __float2bfloat16(v.z - __bfloat162float(h2));
    __nv_bfloat16 l3 = __float2bfloat16(v.w - __bfloat162float(h3));
    hi = pack4bf(h0, h1, h2, h3);
    lo = pack4bf(l0, l1, l2, l3);
}
__device__ __forceinline__ void mma16816(float c[4], const unsigned a[4], const unsigned b[2]) {
    asm volatile(
        "mma.sync.aligned.m16n8k16.row.col.f32.bf16.bf16.f32 "
        "{%0,%1,%2,%3}, {%4,%5,%6,%7}, {%8,%9}, {%0,%1,%2,%3};"
        : "+f"(c[0]), "+f"(c[1]), "+f"(c[2]), "+f"(c[3])
        : "r"(a[0]), "r"(a[1]), "r"(a[2]), "r"(a[3]), "r"(b[0]), "r"(b[1]));
}

#define KP    136                         // K=128 pitch (bf16)
#define KQ    40                          // K=32 pitch (bf16)
#define T64   (64 * KP * 2)               // 17408
#define T128  (128 * KP * 2)              // 34816
#define QTB   (128 * KQ * 2)              // 10240

// k4 (c-tile 64)
#define K4_VHI 0
#define K4_VLO (T64)
#define K4_AHI (2 * T64)
#define K4_ALO (2 * T64 + T128)
#define SMEM_K4 (2 * T64 + 2 * T128)      // 104448

// k1 v (p-tile 64)
#define K1_WHI 0
#define K1_WLO (T128)
#define K1_XHI (2 * T128)
#define K1_XLO (2 * T128 + T64)
#define SMEM_K1 (2 * T128 + 2 * T64)      // 104448

// k1 q/k projection tiles (32 o rows, 128 p rows, K chunk 128)
#define QP_WHI 0
#define QP_WLO (32 * KP * 2)              // 8704
#define QP_XHI (2 * 32 * KP * 2)          // 17408
#define QP_XLO (QP_XHI + T128)            // 52224  (total 87040 <= SMEM_K1)

// eH/eW QK tiles
#define OFF_QHI 0
#define OFF_QLO (QTB)
#define OFF_KHI (2 * QTB)
#define OFF_KLO (3 * QTB)
#define SMEM_E  (128 * 132 * 4)           // 67584

__device__ __forceinline__ void ldfragA(const char* sm, int hiOff, int loOff,
                                        int rb, int k0, int tig, int kp,
                                        unsigned aH[4], unsigned aL[4]) {
    uint32_t o0 = (uint32_t)(rb * kp + k0 + tig * 2) * 2;
    uint32_t o1 = o0 + 8 * kp * 2;
    aH[0] = *(const unsigned*)(sm + hiOff + o0);
    aH[1] = *(const unsigned*)(sm + hiOff + o1);
    aH[2] = *(const unsigned*)(sm + hiOff + o0 + 16);
    aH[3] = *(const unsigned*)(sm + hiOff + o1 + 16);
    aL[0] = *(const unsigned*)(sm + loOff + o0);
    aL[1] = *(const unsigned*)(sm + loOff + o1);
    aL[2] = *(const unsigned*)(sm + loOff + o0 + 16);
    aL[3] = *(const unsigned*)(sm + loOff + o1 + 16);
}
__device__ __forceinline__ void ldfragB(const char* sm, int hiOff, int loOff,
                                        int xb, int k0, int tig, int kp,
                                        unsigned bH[2], unsigned bL[2]) {
    uint32_t o0 = (uint32_t)(xb * kp + k0 + tig * 2) * 2;
    bH[0] = *(const unsigned*)(sm + hiOff + o0);
    bH[1] = *(const unsigned*)(sm + hiOff + o0 + 16);
    bL[0] = *(const unsigned*)(sm + loOff + o0);
    bL[1] = *(const unsigned*)(sm + loOff + o0 + 16);
}

// ---------------- exact 64th-largest, 2 rows, packed counts + early exit -----
__device__ __forceinline__ void topk64x2(const float v[2][4], float thr[2])
{
    unsigned keys[2][4];
    #pragma unroll
    for (int r = 0; r < 2; ++r)
        #pragma unroll
        for (int j = 0; j < 4; ++j) {
            unsigned u = __float_as_uint(v[r][j]);
            keys[r][j] = (u & 0x80000000u) ? ~u : (u | 0x80000000u);
        }
    unsigned prefix[2] = {0, 0};
    unsigned need[2]   = {64, 64};
    unsigned cand[2]   = {128, 128};
    int      ebit[2]   = {0, 0};
    unsigned done = 0;

    for (int bit = 31; bit >= 0; --bit) {
        unsigned packed = 0;
        #pragma unroll
        for (int r = 0; r < 2; ++r) {
            if (!(done & (1u << r))) {
                unsigned want = (prefix[r] >> bit) | 1u;
                unsigned c = 0;
                #pragma unroll
                for (int j = 0; j < 4; ++j)
                    c += (unsigned)((keys[r][j] >> bit) == want);
                packed += c << (8 * r);
            }
        }
        packed = __reduce_add_sync(0xffffffffu, packed);
        #pragma unroll
        for (int r = 0; r < 2; ++r) {
            if (!(done & (1u << r))) {
                unsigned c = (packed >> (8 * r)) & 255u;
                if (c >= need[r]) { prefix[r] |= 1u << bit; cand[r] = c; }
                else              { need[r] -= c; cand[r] -= c; }
                if (cand[r] == need[r]) { done |= 1u << r; ebit[r] = bit; }
            }
        }
        if (done == 3u) break;
    }
    #pragma unroll
    for (int r = 0; r < 2; ++r) {
        unsigned key;
        if (done & (1u << r)) {
            unsigned mn = 0xFFFFFFFFu;
            #pragma unroll
            for (int j = 0; j < 4; ++j) {
                bool match = (((keys[r][j] ^ prefix[r]) >> ebit[r]) == 0);
                unsigned cand_k = match ? keys[r][j] : 0xFFFFFFFFu;
                mn = cand_k < mn ? cand_k : mn;
            }
            key = __reduce_min_sync(0xffffffffu, mn);
        } else {
            key = prefix[r];
        }
        unsigned u = (key & 0x80000000u) ? (key ^ 0x80000000u) : ~key;
        thr[r] = __uint_as_float(u);
    }
}

// ---------------- q/k projection via mma (512 threads, tiny regs) ------------
// Y[b, p, o(32)] = W[32 o][256 c] * X[256 c][128 p] + bias, per block 128 p.
__device__ __forceinline__ void proj_qk_mma_body(
    const float* __restrict__ X, const float* __restrict__ Wm,
    const float* __restrict__ bias, float* __restrict__ Y,
    int b, int p0, char* sm)
{
    const int t = threadIdx.x, wid = t >> 5, lane = t & 31;
    const int gid = lane >> 2, tig = lane & 3;
    const int wr = wid & 1, wc = wid >> 1;    // warp tile: 16 o x 16 p
    float acc[2][4] = {};
    for (int kc = 0; kc < C_; kc += 128) {
        #pragma unroll
        for (int i = 0; i < 2; ++i) {         // W: 1024 float4
            int idx = t + i * 512;
            int o = idx >> 5, c4 = (idx & 31) * 4;
            u64 hi, lo;
            split4(*(const float4*)(Wm + (size_t)o * C_ + kc + c4), hi, lo);
            *(u64*)(sm + QP_WHI + (uint32_t)(o * KP + c4) * 2) = hi;
            *(u64*)(sm + QP_WLO + (uint32_t)(o * KP + c4) * 2) = lo;
        }
        const float* Xb = X + ((size_t)b * C_ + kc) * HW_ + p0;
        #pragma unroll
        for (int i = 0; i < 8; ++i) {         // X: 4096 packs of 4c
            int idx = t + i * 512;
            int c4 = (idx >> 7) * 4, p = idx & 127;
            float4 xv;
            xv.x = Xb[(size_t)(c4 + 0) * HW_ + p];
            xv.y = Xb[(size_t)(c4 + 1) * HW_ + p];
            xv.z = Xb[(size_t)(c4 + 2) * HW_ + p];
            xv.w = Xb[(size_t)(c4 + 3) * HW_ + p];
            u64 hi, lo;
            split4(xv, hi, lo);
            *(u64*)(sm + QP_XHI + (uint32_t)(p * KP + c4) * 2) = hi;
            *(u64*)(sm + QP_XLO + (uint32_t)(p * KP + c4) * 2) = lo;
        }
        __syncthreads();
        #pragma unroll
        for (int ks = 0; ks < 8; ++ks) {
            const int k0 = ks * 16;
            unsigned aH[4], aL[4];
            ldfragA(sm, QP_WHI, QP_WLO, wr * 16 + gid, k0, tig, KP, aH, aL);
            #pragma unroll
            for (int j = 0; j < 2; ++j) {
                unsigned bH[2], bL[2];
                ldfragB(sm, QP_XHI, QP_XLO, wc * 16 + j * 8 + gid, k0, tig, KP, bH, bL);
                mma16816(acc[j], aH, bH);
                mma16816(acc[j], aH, bL);
                mma16816(acc[j], aL, bH);
            }
        }
        __syncthreads();
    }
    float* stage = (float*)sm;                // [128 p][33 o]
    #pragma unroll
    for (int j = 0; j < 2; ++j) {
        int row = wr * 16 + gid;              // o
        int col = wc * 16 + j * 8 + tig * 2;  // p
        stage[col * 33 + row]           = acc[j][0];
        stage[(col + 1) * 33 + row]     = acc[j][1];
        stage[col * 33 + row + 8]       = acc[j][2];
        stage[(col + 1) * 33 + row + 8] = acc[j][3];
    }
    __syncthreads();
    #pragma unroll
    for (int i = 0; i < 2; ++i) {
        int idx = t + i * 512;                // 1024 float4
        int p = idx >> 3, o4 = (idx & 7) * 4;
        float4 r;
        r.x = stage[p * 33 + o4 + 0] + bias[o4 + 0];
        r.y = stage[p * 33 + o4 + 1] + bias[o4 + 1];
        r.z = stage[p * 33 + o4 + 2] + bias[o4 + 2];
        r.w = stage[p * 33 + o4 + 3] + bias[o4 + 3];
        *(float4*)(Y + ((size_t)b * HW_ + p0 + p) * CQ_ + o4) = r;
    }
}

// ---------------- v projection via mma, p-tile 64 ----------------------------
__device__ __forceinline__ void proj_v_mma_body(
    const float* __restrict__ x2, const float* __restrict__ Wv,
    const float* __restrict__ bv, int id, char* sm)
{
    const int b = id >> 9, o0 = ((id >> 8) & 1) * 128, p0 = (id & 255) * 64;
    const int t = threadIdx.x, wid = t >> 5, lane = t & 31;
    const int gid = lane >> 2, tig = lane & 3;
    const int wr = wid & 3, wc = wid >> 2;    // warp tile: 32 o x 16 p

    float acc[2][2][4] = {};
    for (int kc = 0; kc < C_; kc += 128) {
        #pragma unroll
        for (int i = 0; i < 8; ++i) {
            int idx = t + i * 512;
            int o = idx >> 5, c4 = (idx & 31) * 4;
            u64 hi, lo;
            split4(*(const float4*)(Wv + (size_t)(o0 + o) * C_ + kc + c4), hi, lo);
            *(u64*)(sm + K1_WHI + (uint32_t)(o * KP + c4) * 2) = hi;
            *(u64*)(sm + K1_WLO + (uint32_t)(o * KP + c4) * 2) = lo;
        }
        const float* Xb = x2 + ((size_t)b * C_ + kc) * HW_ + p0;
        #pragma unroll
        for (int i = 0; i < 4; ++i) {
            int idx = t + i * 512;
            int c4 = (idx >> 6) * 4, p = idx & 63;
            float4 xv;
            xv.x = Xb[(size_t)(c4 + 0) * HW_ + p];
            xv.y = Xb[(size_t)(c4 + 1) * HW_ + p];
            xv.z = Xb[(size_t)(c4 + 2) * HW_ + p];
            xv.w = Xb[(size_t)(c4 + 3) * HW_ + p];
            u64 hi, lo;
            split4(xv, hi, lo);
            *(u64*)(sm + K1_XHI + (uint32_t)(p * KP + c4) * 2) = hi;
            *(u64*)(sm + K1_XLO + (uint32_t)(p * KP + c4) * 2) = lo;
        }
        __syncthreads();
        #pragma unroll
        for (int ks = 0; ks < 8; ++ks) {
            const int k0 = ks * 16;
            #pragma unroll
            for (int i = 0; i < 2; ++i) {
                unsigned aH[4], aL[4];
                ldfragA(sm, K1_WHI, K1_WLO, wr * 32 + i * 16 + gid, k0, tig, KP, aH, aL);
                #pragma unroll
                for (int j = 0; j < 2; ++j) {
                    unsigned bH[2], bL[2];
                    ldfragB(sm, K1_XHI, K1_XLO, wc * 16 + j * 8 + gid, k0, tig, KP, bH, bL);
                    mma16816(acc[i][j], aH, bH);
                    mma16816(acc[i][j], aH, bL);
                    mma16816(acc[i][j], aL, bH);
                }
            }
        }
        __syncthreads();
    }
    float* stage = (float*)sm;     // [128 o][68 p]
    #pragma unroll
    for (int i = 0; i < 2; ++i)
        #pragma unroll
        for (int j = 0; j < 2; ++j) {
            int row = wr * 32 + i * 16 + gid;
            int col = wc * 16 + j * 8 + tig * 2;
            *(float2*)&stage[row * 68 + col]       = make_float2(acc[i][j][0], acc[i][j][1]);
            *(float2*)&stage[(row + 8) * 68 + col] = make_float2(acc[i][j][2], acc[i][j][3]);
        }
    __syncthreads();
    #pragma unroll
    for (int i = 0; i < 4; ++i) {
        int idx = t + i * 512;
        int o = idx >> 4, p4 = (idx & 15) * 4;
        float bvv = bv[o0 + o];
        float2 u2 = *(float2*)&stage[o * 68 + p4];
        float2 w2 = *(float2*)&stage[o * 68 + p4 + 2];
        *(float4*)(g_v + ((size_t)b * C_ + o0 + o) * HW_ + p0 + p4) =
            make_float4(u2.x + bvv, u2.y + bvv, w2.x + bvv, w2.y + bvv);
    }
}

// ---------------- K1: ALL projections fused (512 threads, 2 CTAs/SM) ---------
// [0,4096): v. [4096,5120): q. [5120,6144): k.
__global__ void __launch_bounds__(512, 2) k1_proj(
    const float* __restrict__ x1, const float* __restrict__ x2,
    const float* __restrict__ Wq, const float* __restrict__ bq,
    const float* __restrict__ Wk, const float* __restrict__ bk,
    const float* __restrict__ Wv, const float* __restrict__ bv)
{
    extern __shared__ __align__(16) char smc[];
    const int id = blockIdx.x;
    if (id < 4096) {
        proj_v_mma_body(x2, Wv, bv, id, smc);
    } else if (id < 5120) {
        int r = id - 4096;
        proj_qk_mma_body(x1, Wq, bq, g_qc, r >> 7, (r & 127) * 128, smc);
    } else {
        int r = id - 5120;
        proj_qk_mma_body(x2, Wk, bk, g_kc, r >> 7, (r & 127) * 128, smc);
    }
}

// ---------------- QK score tile via mma (low liveness) ------------------------
__device__ __forceinline__ void qk_mma(
    const float* __restrict__ qb, const float* __restrict__ kb, size_t rowstride,
    char* sm, float acc[2][4][4])
{
    const int t = threadIdx.x, wid = t >> 5, lane = t & 31;
    const int gid = lane >> 2, tig = lane & 3;
    const int wr = wid & 3, wc = wid >> 2;
    #pragma unroll
    for (int i = 0; i < 2; ++i) {
        int idx = t + i * 512;
        int r = idx >> 3, c4 = (idx & 7) * 4;
        size_t off = (size_t)r * rowstride + c4;
        uint32_t so = (uint32_t)(r * KQ + c4) * 2;
        u64 hi, lo;
        split4(*(const float4*)(qb + off), hi, lo);
        *(u64*)(sm + OFF_QHI + so) = hi;
        *(u64*)(sm + OFF_QLO + so) = lo;
        split4(*(const float4*)(kb + off), hi, lo);
        *(u64*)(sm + OFF_KHI + so) = hi;
        *(u64*)(sm + OFF_KLO + so) = lo;
    }
    __syncthreads();
    #pragma unroll
    for (int ks = 0; ks < 2; ++ks) {
        const int k0 = ks * 16;
        #pragma unroll
        for (int i = 0; i < 2; ++i) {
            unsigned aH[4], aL[4];
            ldfragA(sm, OFF_QHI, OFF_QLO, wr * 32 + i * 16 + gid, k0, tig, KQ, aH, aL);
            #pragma unroll
            for (int j = 0; j < 4; ++j) {
                unsigned bH[2], bL[2];
                ldfragB(sm, OFF_KHI, OFF_KLO, wc * 32 + j * 8 + gid, k0, tig, KQ, bH, bL);
                mma16816(acc[i][j], aH, bH);
                mma16816(acc[i][j], aH, bL);
                mma16816(acc[i][j], aL, bH);
            }
        }
    }
    __syncthreads();
}

// ---------------- eH body (512 threads, mma + topk) ---------------------------
__device__ __forceinline__ void eH_body(int w, int b, char* sm)
{
    const int t = threadIdx.x, wid5 = t >> 5, lane = t & 31;
    const int gid = lane >> 2, tig = lane & 3;
    const int wr = wid5 & 3, wc = wid5 >> 2;
    float acc[2][4][4] = {};
    qk_mma(g_qc + ((size_t)b * HW_ + w) * CQ_,
           g_kc + ((size_t)b * HW_ + w) * CQ_,
           (size_t)W_ * CQ_, sm, acc);
    float* Es = (float*)sm;  // [128][132]
    #pragma unroll
    for (int i = 0; i < 2; ++i)
        #pragma unroll
        for (int j = 0; j < 4; ++j) {
            int row = wr * 32 + i * 16 + gid;
            int col = wc * 32 + j * 8 + tig * 2;
            Es[row * 132 + col]           = (row == col)         ? NEGF : acc[i][j][0];
            Es[row * 132 + col + 1]       = (row == col + 1)     ? NEGF : acc[i][j][1];
            Es[(row + 8) * 132 + col]     = (row + 8 == col)     ? NEGF : acc[i][j][2];
            Es[(row + 8) * 132 + col + 1] = (row + 8 == col + 1) ? NEGF : acc[i][j][3];
        }
    __syncthreads();
    #pragma unroll
    for (int grp = 0; grp < 4; ++grp) {
        float v[2][4];
        int rr[2];
        #pragma unroll
        for (int s = 0; s < 2; ++s) {
            rr[s] = wid5 + 16 * (grp * 2 + s);
            float4 x = *(const float4*)&Es[rr[s] * 132 + lane * 4];
            v[s][0] = x.x; v[s][1] = x.y; v[s][2] = x.z; v[s][3] = x.w;
        }
        float thr[2];
        topk64x2(v, thr);
        #pragma unroll
        for (int s = 0; s < 2; ++s) {
            float4 o;
            o.x = v[s][0] >= thr[s] ? v[s][0] : NEGF;
            o.y = v[s][1] >= thr[s] ? v[s][1] : NEGF;
            o.z = v[s][2] >= thr[s] ? v[s][2] : NEGF;
            o.w = v[s][3] >= thr[s] ? v[s][3] : NEGF;
            *(float4*)(g_att + (((size_t)b * H_ + rr[s]) * W_ + w) * 256 + lane * 4) = o;
        }
    }
}

// ---------------- transpose body: 64x64 tile ----------------------------------
__device__ __forceinline__ void transpose_body(int n, int w0, int h0, float* sm)
{
    float* tile = sm;
    const float* s = g_v  + (size_t)n * HW_;
    float*       d = g_vt + (size_t)n * HW_;
    const int t = threadIdx.x;
    const int col = t & 63, rg = t >> 6;
    #pragma unroll
    for (int i = 0; i < 8; ++i) {
        int row = rg + i * 8;
        tile[row * 65 + col] = s[(size_t)(h0 + row) * W_ + w0 + col];
    }
    __syncthreads();
    #pragma unroll
    for (int i = 0; i < 8; ++i) {
        int row = rg + i * 8;
        d[(size_t)(w0 + row) * H_ + h0 + col] = tile[col * 65 + row];
    }
}

// ---------------- K2: eH + v-transpose fused (2 CTAs/SM) ---------------------
__global__ void __launch_bounds__(512, 2) k2_eH_tr()
{
    extern __shared__ __align__(16) char smc[];
    const int id = blockIdx.x;
    if (id < 1024) {
        eH_body(id & 127, id >> 7, smc);
    } else {
        int r = id - 1024;
        transpose_body(r >> 2, (r & 1) * 64, ((r >> 1) & 1) * 64, (float*)smc);
    }
}

// ---------------- K3: eW (mma) + joint softmax (2 CTAs/SM) --------------------
__global__ void __launch_bounds__(512, 2) k3_eW_softmax()
{
    extern __shared__ __align__(16) char smc[];
    const int h = blockIdx.x & 127, b = blockIdx.x >> 7;
    const int t = threadIdx.x, wid5 = t >> 5, lane = t & 31;
    const int gid = lane >> 2, tig = lane & 3;
    const int wr = wid5 & 3, wc = wid5 >> 2;
    float acc[2][4][4] = {};
    qk_mma(g_qc + ((size_t)b * HW_ + (size_t)h * W_) * CQ_,
           g_kc + ((size_t)b * HW_ + (size_t)h * W_) * CQ_,
           (size_t)CQ_, smc, acc);
    float* Es = (float*)smc;  // [128][132]
    #pragma unroll
    for (int i = 0; i < 2; ++i)
        #pragma unroll
        for (int j = 0; j < 4; ++j) {
            int row = wr * 32 + i * 16 + gid;
            int col = wc * 32 + j * 8 + tig * 2;
            *(float2*)&Es[row * 132 + col]       = make_float2(acc[i][j][0], acc[i][j][1]);
            *(float2*)&Es[(row + 8) * 132 + col] = make_float2(acc[i][j][2], acc[i][j][3]);
        }
    __syncthreads();
    #pragma unroll
    for (int grp = 0; grp < 4; ++grp) {
        float wv[2][4];
        int rr[2];
        #pragma unroll
        for (int s = 0; s < 2; ++s) {
            rr[s] = wid5 + 16 * (grp * 2 + s);
            float4 x = *(const float4*)&Es[rr[s] * 132 + lane * 4];
            wv[s][0] = x.x; wv[s][1] = x.y; wv[s][2] = x.z; wv[s][3] = x.w;
        }
        float thr[2];
        topk64x2(wv, thr);
        float hv[2][4];
        #pragma unroll
        for (int s = 0; s < 2; ++s) {
            #pragma unroll
            for (int j = 0; j < 4; ++j)
                wv[s][j] = (wv[s][j] >= thr[s]) ? wv[s][j] : NEGF;
            float4 x = *(const float4*)(g_att + (((size_t)b * H_ + h) * W_ + rr[s]) * 256 + lane * 4);
            hv[s][0] = x.x; hv[s][1] = x.y; hv[s][2] = x.z; hv[s][3] = x.w;
        }
        float m[2];
        #pragma unroll
        for (int s = 0; s < 2; ++s) {
            m[s] = NEGF;
            #pragma unroll
            for (int j = 0; j < 4; ++j) m[s] = fmaxf(m[s], fmaxf(wv[s][j], hv[s][j]));
        }
        #pragma unroll
        for (int off = 16; off; off >>= 1)
            #pragma unroll
            for (int s = 0; s < 2; ++s)
                m[s] = fmaxf(m[s], __shfl_xor_sync(0xffffffffu, m[s], off));
        float ph[2][4], pw[2][4], sum[2];
        #pragma unroll
        for (int s = 0; s < 2; ++s) {
            sum[s] = 0.f;
            #pragma unroll
            for (int j = 0; j < 4; ++j) {
                ph[s][j] = __expf(hv[s][j] - m[s]);
                pw[s][j] = __expf(wv[s][j] - m[s]);
                sum[s] += ph[s][j] + pw[s][j];
            }
        }
        #pragma unroll
        for (int off = 16; off; off >>= 1)
            #pragma unroll
            for (int s = 0; s < 2; ++s)
                sum[s] += __shfl_xor_sync(0xffffffffu, sum[s], off);
        #pragma unroll
        for (int s = 0; s < 2; ++s) {
            float inv = 1.0f / sum[s];
            float* arow = g_att + (((size_t)b * H_ + h) * W_ + rr[s]) * 256;
            *(float4*)(arow + lane * 4) =
                make_float4(ph[s][0]*inv, ph[s][1]*inv, ph[s][2]*inv, ph[s][3]*inv);
            *(float4*)(arow + 128 + lane * 4) =
                make_float4(pw[s][0]*inv, pw[s][1]*inv, pw[s][2]*inv, pw[s][3]*inv);
        }
    }
}

// ---------------- K4: AV GEMM via mma, c-tile 64, 2 CTAs/SM ------------------
template<bool HSIDE>
__device__ __forceinline__ void av_mma_body(int c0, int p, int b, char* sm)
{
    const int t = threadIdx.x, wid = t >> 5, lane = t & 31;
    const int gid = lane >> 2, tig = lane & 3;
    const int wr = wid & 3, wc = wid >> 2;   // warp tile: 16 c x 32 x

    const float* vbase = HSIDE ? g_vt + (((size_t)b * C_ + c0) * W_ + p) * H_
                               : g_v  + (((size_t)b * C_ + c0) * H_ + p) * W_;
    const float* abase = HSIDE ? g_att + ((size_t)b * HW_ + p) * 256
                               : g_att + (((size_t)b * H_ + p) * W_) * 256 + 128;
    const size_t astride = HSIDE ? (size_t)W_ * 256 : 256;

    #pragma unroll
    for (int i = 0; i < 4; ++i) {            // V: 64x128 = 2048 float4
        int idx = t + i * 512;
        int r = idx >> 5, g4 = (idx & 31) * 4;
        uint32_t so = (uint32_t)(r * KP + g4) * 2;
        u64 hi, lo;
        split4(*(const float4*)(vbase + (size_t)r * HW_ + g4), hi, lo);
        *(u64*)(sm + K4_VHI + so) = hi;
        *(u64*)(sm + K4_VLO + so) = lo;
    }
    #pragma unroll
    for (int i = 0; i < 8; ++i) {            // A: 128x128 = 4096 float4
        int idx = t + i * 512;
        int r = idx >> 5, g4 = (idx & 31) * 4;
        uint32_t so = (uint32_t)(r * KP + g4) * 2;
        u64 hi, lo;
        split4(*(const float4*)(abase + (size_t)r * astride + g4), hi, lo);
        *(u64*)(sm + K4_AHI + so) = hi;
        *(u64*)(sm + K4_ALO + so) = lo;
    }
    __syncthreads();

    float acc[4][4] = {};
    #pragma unroll
    for (int ks = 0; ks < 8; ++ks) {
        const int k0 = ks * 16;
        unsigned aH[4], aL[4];
        ldfragA(sm, K4_VHI, K4_VLO, wr * 16 + gid, k0, tig, KP, aH, aL);
        #pragma unroll
        for (int j = 0; j < 4; ++j) {
            unsigned bH[2], bL[2];
            ldfragB(sm, K4_AHI, K4_ALO, wc * 32 + j * 8 + gid, k0, tig, KP, bH, bL);
            mma16816(acc[j], aH, bH);
            mma16816(acc[j], aH, bL);
            mma16816(acc[j], aL, bH);
        }
    }
    __syncthreads();

    float* stage = (float*)sm;   // [64][132]
    #pragma unroll
    for (int j = 0; j < 4; ++j) {
        int row = wr * 16 + gid;
        int col = wc * 32 + j * 8 + tig * 2;
        *(float2*)&stage[row * 132 + col]       = make_float2(acc[j][0], acc[j][1]);
        *(float2*)&stage[(row + 8) * 132 + col] = make_float2(acc[j][2], acc[j][3]);
    }
    __syncthreads();

    float* dstbase = HSIDE ? g_oht + (((size_t)b * C_ + c0) * W_ + p) * H_
                           : g_ow  + (((size_t)b * C_ + c0) * H_ + p) * W_;
    #pragma unroll
    for (int i = 0; i < 4; ++i) {            // 64x128 = 2048 float4
        int idx = t + i * 512;
        int r = idx >> 5, x4 = (idx & 31) * 4;
        float2 u2 = *(float2*)&stage[r * 132 + x4];
        float2 w2 = *(float2*)&stage[r * 132 + x4 + 2];
        *(float4*)(dstbase + (size_t)r * HW_ + x4) = make_float4(u2.x, u2.y, w2.x, w2.y);
    }
}

__global__ void __launch_bounds__(512, 2) k4_out()
{
    extern __shared__ __align__(16) char smc[];
    int id = blockIdx.x;
    if (id < 4096) {
        av_mma_body<true >((id & 3) * 64, (id >> 2) & 127, id >> 9, smc);
    } else {
        id -= 4096;
        av_mma_body<false>((id & 3) * 64, (id >> 2) & 127, id >> 9, smc);
    }
}

// ---------------- K5: out = gamma*(outH^T + outW) + x1 -----------------------
__global__ void __launch_bounds__(256) k5_combine(
    const float* __restrict__ x1, const float* __restrict__ gamma,
    float* __restrict__ out)
{
    __shared__ float tile[32][33];
    const size_t n = blockIdx.z;
    const float* oht = g_oht + n * HW_;
    const float* ow  = g_ow  + n * HW_;
    const float* x   = x1    + n * HW_;
    float*       o   = out   + n * HW_;
    const int w0 = blockIdx.x * 32, h0 = blockIdx.y * 32;
    const int tx = threadIdx.x, ty = threadIdx.y;
    #pragma unroll
    for (int i = ty; i < 32; i += 8)
        tile[i][tx] = oht[(size_t)(w0 + i) * H_ + h0 + tx];
    __syncthreads();
    const float gm = gamma[0];
    #pragma unroll
    for (int i = ty; i < 32; i += 8) {
        size_t idx = (size_t)(h0 + i) * W_ + w0 + tx;
        o[idx] = gm * (tile[tx][i] + ow[idx]) + x[idx];
    }
}

// ---------------- launch ------------------------------------------------------
extern "C" void kernel_launch(void* const* d_in, const int* in_sizes, int n_in,
                              void* d_out, int out_size)
{
    (void)in_sizes; (void)n_in; (void)out_size;
    const float* x1    = (const float*)d_in[0];
    const float* x2    = (const float*)d_in[1];
    const float* Wq    = (const float*)d_in[2];
    const float* bq    = (const float*)d_in[3];
    const float* Wk    = (const float*)d_in[4];
    const float* bk    = (const float*)d_in[5];
    const float* Wv    = (const float*)d_in[6];
    const float* bv    = (const float*)d_in[7];
    const float* gamma = (const float*)d_in[8];
    float* out = (float*)d_out;

    cudaFuncSetAttribute(k1_proj,       cudaFuncAttributeMaxDynamicSharedMemorySize, SMEM_K1);
    cudaFuncSetAttribute(k2_eH_tr,      cudaFuncAttributeMaxDynamicSharedMemorySize, SMEM_E);
    cudaFuncSetAttribute(k3_eW_softmax, cudaFuncAttributeMaxDynamicSharedMemorySize, SMEM_E);
    cudaFuncSetAttribute(k4_out,        cudaFuncAttributeMaxDynamicSharedMemorySize, SMEM_K4);

    k1_proj      <<<6144, 512, SMEM_K1>>>(x1, x2, Wq, bq, Wk, bk, Wv, bv);
    k2_eH_tr     <<<1024 + 8192, 512, SMEM_E>>>();
    k3_eW_softmax<<<1024, 512, SMEM_E>>>();
    k4_out       <<<8192, 512, SMEM_K4>>>();
    k5_combine   <<<dim3(4, 4, B_*C_), dim3(32, 8)>>>(x1, gamma, out);
}